// round 1
// baseline (speedup 1.0000x reference)
#include <cuda_runtime.h>
#include <math.h>

// Problem constants
static constexpr int BN = 4;            // batch
static constexpr int NC = 21;           // classes
static constexpr int H  = 512;
static constexpr int W  = 512;
static constexpr int P  = 171;          // pooled H/W  (floor((512+2-3)/3)+1)
static constexpr int NH = 169;          // cropped size P - (radius-1)
static constexpr int NPROB = BN * NC;   // 84
static constexpr int MM = NH * NH;      // 28561
static constexpr double D_ALPHA = 5e-4;
static constexpr float  CLIP_MIN = 1e-6f;
static constexpr int SPITCH = 173;      // smem pitch (odd -> bank spread)

// Scratch (static device globals: no allocation allowed)
__device__ float  g_la[NPROB * P * P];      // pooled one-hot labels
__device__ float  g_pr[NPROB * P * P];      // pooled probs
__device__ double g_S[NPROB * 18 * 18];     // raw second-moment Gram (lower tri)
__device__ double g_sums[NPROB * 18];       // raw first moments (per shifted view)
__device__ double g_rmi[NPROB];
__device__ double g_bce;
__device__ double g_valid;

// lower-triangle 3x3-tile map of the 6x6 tile grid (21 tiles)
__constant__ int c_TI[21] = {0,1,1,2,2,2,3,3,3,3,4,4,4,4,4,5,5,5,5,5,5};
__constant__ int c_TJ[21] = {0,0,1,0,1,2,0,1,2,3,0,1,2,3,4,0,1,2,3,4,5};

// ---------------------------------------------------------------------------
__global__ void k_init() {
    int i = blockIdx.x * blockDim.x + threadIdx.x;
    if (i < NPROB * 18 * 18) g_S[i] = 0.0;
    if (i == 0) { g_bce = 0.0; g_valid = 0.0; }
}

// ---------------------------------------------------------------------------
// Fused: BCE partial sums + sigmoid + one-hot + 3x3/s3/p1 maxpool.
// One thread per pooled output pixel (n,c,py,px). Windows partition the input,
// so each (pixel,class) BCE term is counted exactly once.
__global__ void __launch_bounds__(256) k_pool_bce(const float* __restrict__ logits,
                                                  const int*   __restrict__ labels) {
    int idx = blockIdx.x * blockDim.x + threadIdx.x;
    float bce_part = 0.f, valid_part = 0.f;
    if (idx < NPROB * P * P) {
        int px = idx % P;
        int t  = idx / P;
        int py = t % P;  t /= P;
        int c  = t % NC;
        int n  = t / NC;
        const float* lg = logits + (long)(n * NC + c) * H * W;
        const int*   lb = labels + (long)n * H * W;
        float mla = 0.f;   // one-hot values >= 0, every window has >=4 valid pixels
        float mpr = 0.f;   // probs >= 1e-6 > 0
        int y0 = py * 3 - 1, x0 = px * 3 - 1;
#pragma unroll
        for (int dy = 0; dy < 3; dy++) {
            int y = y0 + dy;
            if ((unsigned)y >= (unsigned)H) continue;
#pragma unroll
            for (int dx = 0; dx < 3; dx++) {
                int x = x0 + dx;
                if ((unsigned)x >= (unsigned)W) continue;
                int   lab = lb[y * W + x];
                float m   = (lab < NC) ? 1.f : 0.f;
                float t1  = (lab == c) ? m : 0.f;     // masked one-hot
                float xv  = lg[y * W + x];
                float ax  = fabsf(xv);
                float e   = __expf(-ax);
                // stable bce-with-logits, weight = mask
                bce_part += (fmaxf(xv, 0.f) - xv * t1 + log1pf(e)) * m;
                float sig = (xv >= 0.f) ? (1.f / (1.f + e)) : (e / (1.f + e));
                float pb  = fmaf(sig, m, CLIP_MIN);
                mpr = fmaxf(mpr, pb);
                mla = fmaxf(mla, t1);
                if (c == 0) valid_part += m;          // count each pixel once
            }
        }
        g_la[idx] = mla;
        g_pr[idx] = mpr;
    }
    __shared__ float rb[256], rv[256];
    int tid = threadIdx.x;
    rb[tid] = bce_part; rv[tid] = valid_part;
    __syncthreads();
    for (int s = 128; s > 0; s >>= 1) {
        if (tid < s) { rb[tid] += rb[tid + s]; rv[tid] += rv[tid + s]; }
        __syncthreads();
    }
    if (tid == 0) {
        atomicAdd(&g_bce,   (double)rb[0]);
        atomicAdd(&g_valid, (double)rv[0]);
    }
}

// ---------------------------------------------------------------------------
// First moments of the 9 shifted views of each pooled map (rectangle sums).
__global__ void __launch_bounds__(256) k_sums() {
    int p = blockIdx.x;
    const float* la = g_la + p * P * P;
    const float* pr = g_pr + p * P * P;
    float sl[9], sp[9];
#pragma unroll
    for (int d = 0; d < 9; d++) { sl[d] = 0.f; sp[d] = 0.f; }
    for (int i = threadIdx.x; i < P * P; i += 256) {
        int y = i / P, x = i - y * P;
        float vl = la[i], vp = pr[i];
#pragma unroll
        for (int d = 0; d < 9; d++) {
            int dy = d / 3, dx = d % 3;
            if ((unsigned)(y - dy) < (unsigned)NH && (unsigned)(x - dx) < (unsigned)NH) {
                sl[d] += vl; sp[d] += vp;
            }
        }
    }
    __shared__ double sd[18];
    if (threadIdx.x < 18) sd[threadIdx.x] = 0.0;
    __syncthreads();
#pragma unroll
    for (int d = 0; d < 9; d++) {
        atomicAdd(&sd[d],     (double)sl[d]);
        atomicAdd(&sd[9 + d], (double)sp[d]);
    }
    __syncthreads();
    if (threadIdx.x < 18) g_sums[p * 18 + threadIdx.x] = sd[threadIdx.x];
}

// ---------------------------------------------------------------------------
// Gram matrix S = X X^T lower triangle, X = [18 x 28561] (9 la rows + 9 pr rows).
// Block = (problem, y-strip). 189 active threads = 21 lower-tri 3x3 tiles x 9 m-groups.
__global__ void __launch_bounds__(192) k_cov() {
    int p     = blockIdx.x;
    int strip = blockIdx.y;
    int ylo = strip * 22;
    int yhi = min(NH, ylo + 22);
    __shared__ float  s[18 * SPITCH];
    __shared__ double sacc[189];
    int  tid    = threadIdx.x;
    bool active = tid < 189;
    int  tile   = active ? tid / 9 : 0;
    int  mg     = tid % 9;
    int  r0 = c_TI[tile] * 3, c0 = c_TJ[tile] * 3;
    int  xs = mg * 19;
    int  xe = min(NH, xs + 19);
    const float* la = g_la + p * P * P;
    const float* pr = g_pr + p * P * P;
    float  f[9]; double dacc[9];
#pragma unroll
    for (int q = 0; q < 9; q++) { f[q] = 0.f; dacc[q] = 0.0; }

    for (int y = ylo; y < yhi; y++) {
        // stage the 18 shifted rows for this y into smem
        for (int i = tid; i < 18 * NH; i += 192) {
            int dd = i / NH;
            int x  = i - dd * NH;
            int d9 = (dd < 9) ? dd : dd - 9;
            const float* src = (dd < 9) ? la : pr;
            s[dd * SPITCH + x] = src[(y + d9 / 3) * P + (x + d9 % 3)];
        }
        __syncthreads();
        if (active) {
            const float* sa = s + r0 * SPITCH;
            const float* sb = s + c0 * SPITCH;
            for (int x = xs; x < xe; x++) {
                float a0 = sa[x], a1 = sa[SPITCH + x], a2 = sa[2 * SPITCH + x];
                float b0 = sb[x], b1 = sb[SPITCH + x], b2 = sb[2 * SPITCH + x];
                f[0] += a0 * b0; f[1] += a0 * b1; f[2] += a0 * b2;
                f[3] += a1 * b0; f[4] += a1 * b1; f[5] += a1 * b2;
                f[6] += a2 * b0; f[7] += a2 * b1; f[8] += a2 * b2;
            }
#pragma unroll
            for (int q = 0; q < 9; q++) { dacc[q] += (double)f[q]; f[q] = 0.f; }
        }
        __syncthreads();
    }
    if (tid < 189) sacc[tid] = 0.0;
    __syncthreads();
    if (active) {
#pragma unroll
        for (int q = 0; q < 9; q++) atomicAdd(&sacc[tile * 9 + q], dacc[q]);
    }
    __syncthreads();
    if (tid < 189) {
        int tl = tid / 9, q = tid % 9;
        int i = c_TI[tl] * 3 + q / 3;
        int j = c_TJ[tl] * 3 + q % 3;
        atomicAdd(&g_S[p * 324 + i * 18 + j], sacc[tid]);
    }
}

// ---------------------------------------------------------------------------
// Warp-parallel 9x9 Cholesky (lower, in place, smem doubles)
__device__ __forceinline__ void chol9(double* A, int lane) {
    for (int k = 0; k < 9; k++) {
        if (lane == 0) A[k * 9 + k] = sqrt(A[k * 9 + k]);
        __syncwarp();
        double dk = A[k * 9 + k];
        if (lane > k && lane < 9) A[lane * 9 + k] /= dk;
        __syncwarp();
        for (int idx = lane; idx < 81; idx += 32) {
            int i = idx / 9, j = idx % 9;
            if (j > k && j <= i) A[i * 9 + j] -= A[i * 9 + k] * A[j * 9 + k];
        }
        __syncwarp();
    }
}

// One warp per (n,c) problem: build covariances from raw moments (double
// correction), Cholesky-solve for cross*inv(pr_cov+aI)*cross^T, logdet.
__global__ void __launch_bounds__(32) k_solve() {
    int p    = blockIdx.x;
    int lane = threadIdx.x;
    __shared__ double A[81], B[81], C2[81], V[81];
    const double* S  = g_S    + p * 324;
    const double* sm = g_sums + p * 18;
    const double invM = 1.0 / (double)MM;
    for (int idx = lane; idx < 81; idx += 32) {
        int i = idx / 9, j = idx % 9;
        int a = 9 + i, b = 9 + j;
        int hi = a > b ? a : b, lo = a > b ? b : a;
        A[idx] = S[hi * 18 + lo] - sm[a] * sm[b] * invM + (i == j ? D_ALPHA : 0.0); // pr_cov+aI
        B[idx] = S[(9 + j) * 18 + i] - sm[i] * sm[9 + j] * invM;                    // cross[d][e]
        hi = i > j ? i : j; lo = i > j ? j : i;
        C2[idx] = S[hi * 18 + lo] - sm[i] * sm[j] * invM;                           // la_cov
    }
    __syncwarp();
    chol9(A, lane);
    // forward solve L V = cross^T   (column d per lane)
    if (lane < 9) {
        int d = lane;
        for (int e = 0; e < 9; e++) {
            double t = B[d * 9 + e];
            for (int j = 0; j < e; j++) t -= A[e * 9 + j] * V[j * 9 + d];
            V[e * 9 + d] = t / A[e * 9 + e];
        }
    }
    __syncwarp();
    // appro_var = la_cov - V^T V + aI   (reuse B)
    for (int idx = lane; idx < 81; idx += 32) {
        int i = idx / 9, j = idx % 9;
        double t = C2[idx];
#pragma unroll
        for (int k = 0; k < 9; k++) t -= V[k * 9 + i] * V[k * 9 + j];
        if (i == j) t += D_ALPHA;
        B[idx] = t;
    }
    __syncwarp();
    chol9(B, lane);
    double lsum = (lane < 9) ? log(B[lane * 9 + lane]) : 0.0;  // 0.5*logdet = sum log diag
    for (int off = 16; off > 0; off >>= 1)
        lsum += __shfl_down_sync(0xffffffffu, lsum, off);
    if (lane == 0) g_rmi[p] = lsum;
}

// ---------------------------------------------------------------------------
__global__ void k_final(float* out) {
    __shared__ double sm[128];
    int t = threadIdx.x;
    sm[t] = (t < NPROB) ? g_rmi[t] : 0.0;
    __syncthreads();
    for (int s = 64; s > 0; s >>= 1) {
        if (t < s) sm[t] += sm[t + s];
        __syncthreads();
    }
    if (t == 0) {
        double rmi = sm[0] / 36.0;                  // mean over batch(4) / half_d(9), summed over classes
        double bce = g_bce / (g_valid + 1.0);
        out[0] = (float)(0.5 * bce + 0.5 * rmi);
    }
}

// ---------------------------------------------------------------------------
extern "C" void kernel_launch(void* const* d_in, const int* in_sizes, int n_in,
                              void* d_out, int out_size) {
    const float* logits = (const float*)d_in[0];
    const int*   labels = (const int*)d_in[1];
    float* out = (float*)d_out;

    k_init<<<(NPROB * 324 + 255) / 256, 256>>>();
    int tot = NPROB * P * P;
    k_pool_bce<<<(tot + 255) / 256, 256>>>(logits, labels);
    k_sums<<<NPROB, 256>>>();
    k_cov<<<dim3(NPROB, 8), 192>>>();
    k_solve<<<NPROB, 32>>>();
    k_final<<<1, 128>>>(out);
}

// round 2
// speedup vs baseline: 1.4323x; 1.4323x over previous
#include <cuda_runtime.h>
#include <math.h>

// Problem constants
static constexpr int BN = 4;            // batch
static constexpr int NC = 21;           // classes
static constexpr int H  = 512;
static constexpr int W  = 512;
static constexpr int P  = 171;          // pooled H/W
static constexpr int NH = 169;          // cropped size P - (radius-1)
static constexpr int NPROB = BN * NC;   // 84
static constexpr int MM = NH * NH;      // 28561
static constexpr double D_ALPHA = 5e-4;
static constexpr float  CLIP_MIN = 1e-6f;
static constexpr int SPITCH = 173;      // smem pitch (odd -> bank spread)
static constexpr int SH = 16;           // strip height for k_cov
static constexpr int NSTRIP = (NH + SH - 1) / SH;  // 11

// Scratch (static device globals: no allocation allowed)
__device__ float  g_la[NPROB * P * P];      // pooled one-hot labels
__device__ float  g_pr[NPROB * P * P];      // pooled probs
__device__ double g_S[NPROB * 18 * 18];     // raw second-moment Gram (lower tri)
__device__ double g_sums[NPROB * 18];       // raw first moments (per shifted view)
__device__ double g_rmi[NPROB];
__device__ double g_bce;
__device__ double g_valid;

// lower-triangle 3x3-tile map of the 6x6 tile grid (21 tiles)
__constant__ int c_TI[21] = {0,1,1,2,2,2,3,3,3,3,4,4,4,4,4,5,5,5,5,5,5};
__constant__ int c_TJ[21] = {0,0,1,0,1,2,0,1,2,3,0,1,2,3,4,0,1,2,3,4,5};

// ---------------------------------------------------------------------------
__global__ void k_init() {
    int i = blockIdx.x * blockDim.x + threadIdx.x;
    if (i < NPROB * 18 * 18) g_S[i] = 0.0;
    if (i == 0) { g_bce = 0.0; g_valid = 0.0; }
}

// ---------------------------------------------------------------------------
// Fused: BCE partial sums + sigmoid + one-hot + 3x3/s3/p1 maxpool.
// Block = (py, n); thread = px; loops all 21 classes so labels are read ONCE.
__global__ void __launch_bounds__(192) k_pool_bce(const float* __restrict__ logits,
                                                  const int*   __restrict__ labels) {
    int py = blockIdx.x;        // 0..170
    int n  = blockIdx.y;        // 0..3
    int px = threadIdx.x;       // active < 171
    float bce_part = 0.f, valid_part = 0.f;

    if (px < P) {
        const int* lb = labels + (long)n * H * W;
        int y0 = py * 3 - 1, x0 = px * 3 - 1;
        int   lab[9];
        float mk[9];
        bool  vld[9];
#pragma unroll
        for (int k = 0; k < 9; k++) {
            int y = y0 + k / 3, x = x0 + k % 3;
            bool v = ((unsigned)y < (unsigned)H) && ((unsigned)x < (unsigned)W);
            vld[k] = v;
            int l = v ? lb[y * W + x] : NC;
            lab[k] = l;
            float m = (l < NC) ? 1.f : 0.f;
            mk[k] = m;
            valid_part += m;              // each input pixel counted exactly once
        }
        long ppp = (long)P * P;
        for (int c = 0; c < NC; c++) {
            const float* lg = logits + (long)(n * NC + c) * H * W;
            float mla = 0.f, mpr = 0.f;
#pragma unroll
            for (int k = 0; k < 9; k++) {
                int y = y0 + k / 3, x = x0 + k % 3;
                float xv = vld[k] ? lg[y * W + x] : 0.f;
                float m  = mk[k];
                float t1 = (lab[k] == c) ? m : 0.f;
                float ax = fabsf(xv);
                float e  = __expf(-ax);
                // stable bce-with-logits, weight = mask (fast log: 1+e in [1,2])
                bce_part += (fmaxf(xv, 0.f) - xv * t1 + __logf(1.f + e)) * m;
                float r   = __fdividef(1.f, 1.f + e);
                float sig = (xv >= 0.f) ? r : e * r;
                float pb  = fmaf(sig, m, CLIP_MIN);
                mpr = fmaxf(mpr, pb);     // windows always contain >=4 valid pixels
                mla = fmaxf(mla, t1);
            }
            long o = (long)(n * NC + c) * ppp + (long)py * P + px;
            g_la[o] = mla;
            g_pr[o] = mpr;
        }
    }
    __shared__ float rb[192], rv[192];
    int tid = threadIdx.x;
    rb[tid] = bce_part; rv[tid] = valid_part;
    __syncthreads();
    for (int s = 96; s > 0; s >>= 1) {
        if (tid < s) { rb[tid] += rb[tid + s]; rv[tid] += rv[tid + s]; }
        __syncthreads();
    }
    if (tid == 0) {
        atomicAdd(&g_bce,   (double)rb[0]);
        atomicAdd(&g_valid, (double)rv[0]);
    }
}

// ---------------------------------------------------------------------------
// First moments of the 9 shifted views of each pooled map (rectangle sums).
__global__ void __launch_bounds__(256) k_sums() {
    int p = blockIdx.x;
    const float* la = g_la + p * P * P;
    const float* pr = g_pr + p * P * P;
    float sl[9], sp[9];
#pragma unroll
    for (int d = 0; d < 9; d++) { sl[d] = 0.f; sp[d] = 0.f; }
    for (int i = threadIdx.x; i < P * P; i += 256) {
        int y = i / P, x = i - y * P;
        float vl = la[i], vp = pr[i];
#pragma unroll
        for (int d = 0; d < 9; d++) {
            int dy = d / 3, dx = d % 3;
            if ((unsigned)(y - dy) < (unsigned)NH && (unsigned)(x - dx) < (unsigned)NH) {
                sl[d] += vl; sp[d] += vp;
            }
        }
    }
    __shared__ double sd[18];
    if (threadIdx.x < 18) sd[threadIdx.x] = 0.0;
    __syncthreads();
#pragma unroll
    for (int d = 0; d < 9; d++) {
        atomicAdd(&sd[d],     (double)sl[d]);
        atomicAdd(&sd[9 + d], (double)sp[d]);
    }
    __syncthreads();
    if (threadIdx.x < 18) g_sums[p * 18 + threadIdx.x] = sd[threadIdx.x];
}

// ---------------------------------------------------------------------------
// Gram matrix S = X X^T lower triangle, X = [18 x 28561].
// The 18 rows of X are 6 row-streams (la/pr x dy=0..2) at lags dx=0..2, so a
// 3x3 tile's operands are *consecutive* smem elements -> sliding window:
// 2 LDS per 9 FFMA. One strip of SH base rows staged per block; single sync.
__global__ void __launch_bounds__(192) k_cov() {
    int p     = blockIdx.x;
    int strip = blockIdx.y;
    int ys = strip * SH;
    int sh = min(SH, NH - ys);

    __shared__ float  sla[(SH + 2) * SPITCH];
    __shared__ float  spr[(SH + 2) * SPITCH];
    __shared__ double sacc[189];

    int tid = threadIdx.x;
    const float* la = g_la + p * P * P;
    const float* pr = g_pr + p * P * P;

    int nrows = sh + 2;
    for (int i = tid; i < nrows * P; i += 192) {
        int r = i / P, x = i - r * P;
        sla[r * SPITCH + x] = la[(ys + r) * P + x];
        spr[r * SPITCH + x] = pr[(ys + r) * P + x];
    }
    __syncthreads();

    bool active = tid < 189;
    float  f[9];
    double dacc[9];
#pragma unroll
    for (int q = 0; q < 9; q++) { f[q] = 0.f; dacc[q] = 0.0; }

    if (active) {
        int tile = tid / 9, mg = tid % 9;
        int ti = c_TI[tile], tj = c_TJ[tile];
        const float* baseA = ((ti < 3) ? sla : spr) + (ti % 3) * SPITCH;
        const float* baseB = ((tj < 3) ? sla : spr) + (tj % 3) * SPITCH;
        int xs = mg * 19;
        int xe = min(NH, xs + 19);
        for (int y = 0; y < sh; y++) {
            const float* rA = baseA + y * SPITCH;
            const float* rB = baseB + y * SPITCH;
            float a0 = rA[xs], a1 = rA[xs + 1];
            float b0 = rB[xs], b1 = rB[xs + 1];
#pragma unroll 3
            for (int x = xs; x < xe; x++) {
                float a2 = rA[x + 2], b2 = rB[x + 2];
                f[0] += a0 * b0; f[1] += a0 * b1; f[2] += a0 * b2;
                f[3] += a1 * b0; f[4] += a1 * b1; f[5] += a1 * b2;
                f[6] += a2 * b0; f[7] += a2 * b1; f[8] += a2 * b2;
                a0 = a1; a1 = a2; b0 = b1; b1 = b2;
            }
        }
#pragma unroll
        for (int q = 0; q < 9; q++) dacc[q] += (double)f[q];
    }

    if (tid < 189) sacc[tid] = 0.0;
    __syncthreads();
    if (active) {
        int tile = tid / 9;
#pragma unroll
        for (int q = 0; q < 9; q++) atomicAdd(&sacc[tile * 9 + q], dacc[q]);
    }
    __syncthreads();
    if (tid < 189) {
        int tl = tid / 9, q = tid % 9;
        int i = c_TI[tl] * 3 + q / 3;
        int j = c_TJ[tl] * 3 + q % 3;
        atomicAdd(&g_S[p * 324 + i * 18 + j], sacc[tid]);
    }
}

// ---------------------------------------------------------------------------
// Warp-parallel 9x9 Cholesky (lower, in place, smem doubles)
__device__ __forceinline__ void chol9(double* A, int lane) {
    for (int k = 0; k < 9; k++) {
        if (lane == 0) A[k * 9 + k] = sqrt(A[k * 9 + k]);
        __syncwarp();
        double dk = A[k * 9 + k];
        if (lane > k && lane < 9) A[lane * 9 + k] /= dk;
        __syncwarp();
        for (int idx = lane; idx < 81; idx += 32) {
            int i = idx / 9, j = idx % 9;
            if (j > k && j <= i) A[i * 9 + j] -= A[i * 9 + k] * A[j * 9 + k];
        }
        __syncwarp();
    }
}

// One warp per (n,c) problem: build covariances from raw moments (double
// correction), Cholesky-solve for cross*inv(pr_cov+aI)*cross^T, logdet.
__global__ void __launch_bounds__(32) k_solve() {
    int p    = blockIdx.x;
    int lane = threadIdx.x;
    __shared__ double A[81], B[81], C2[81], V[81];
    const double* S  = g_S    + p * 324;
    const double* sm = g_sums + p * 18;
    const double invM = 1.0 / (double)MM;
    for (int idx = lane; idx < 81; idx += 32) {
        int i = idx / 9, j = idx % 9;
        int a = 9 + i, b = 9 + j;
        int hi = a > b ? a : b, lo = a > b ? b : a;
        A[idx] = S[hi * 18 + lo] - sm[a] * sm[b] * invM + (i == j ? D_ALPHA : 0.0); // pr_cov+aI
        B[idx] = S[(9 + j) * 18 + i] - sm[i] * sm[9 + j] * invM;                    // cross[d][e]
        hi = i > j ? i : j; lo = i > j ? j : i;
        C2[idx] = S[hi * 18 + lo] - sm[i] * sm[j] * invM;                           // la_cov
    }
    __syncwarp();
    chol9(A, lane);
    // forward solve L V = cross^T   (column d per lane)
    if (lane < 9) {
        int d = lane;
        for (int e = 0; e < 9; e++) {
            double t = B[d * 9 + e];
            for (int j = 0; j < e; j++) t -= A[e * 9 + j] * V[j * 9 + d];
            V[e * 9 + d] = t / A[e * 9 + e];
        }
    }
    __syncwarp();
    // appro_var = la_cov - V^T V + aI   (reuse B)
    for (int idx = lane; idx < 81; idx += 32) {
        int i = idx / 9, j = idx % 9;
        double t = C2[idx];
#pragma unroll
        for (int k = 0; k < 9; k++) t -= V[k * 9 + i] * V[k * 9 + j];
        if (i == j) t += D_ALPHA;
        B[idx] = t;
    }
    __syncwarp();
    chol9(B, lane);
    double lsum = (lane < 9) ? log(B[lane * 9 + lane]) : 0.0;  // 0.5*logdet
    for (int off = 16; off > 0; off >>= 1)
        lsum += __shfl_down_sync(0xffffffffu, lsum, off);
    if (lane == 0) g_rmi[p] = lsum;
}

// ---------------------------------------------------------------------------
__global__ void k_final(float* out) {
    __shared__ double sm[128];
    int t = threadIdx.x;
    sm[t] = (t < NPROB) ? g_rmi[t] : 0.0;
    __syncthreads();
    for (int s = 64; s > 0; s >>= 1) {
        if (t < s) sm[t] += sm[t + s];
        __syncthreads();
    }
    if (t == 0) {
        double rmi = sm[0] / 36.0;                  // mean over batch(4)/half_d(9)
        double bce = g_bce / (g_valid + 1.0);
        out[0] = (float)(0.5 * bce + 0.5 * rmi);
    }
}

// ---------------------------------------------------------------------------
extern "C" void kernel_launch(void* const* d_in, const int* in_sizes, int n_in,
                              void* d_out, int out_size) {
    const float* logits = (const float*)d_in[0];
    const int*   labels = (const int*)d_in[1];
    float* out = (float*)d_out;

    k_init<<<(NPROB * 324 + 255) / 256, 256>>>();
    k_pool_bce<<<dim3(P, BN), 192>>>(logits, labels);
    k_sums<<<NPROB, 256>>>();
    k_cov<<<dim3(NPROB, NSTRIP), 192>>>();
    k_solve<<<NPROB, 32>>>();
    k_final<<<1, 128>>>(out);
}

// round 3
// speedup vs baseline: 2.7083x; 1.8909x over previous
#include <cuda_runtime.h>
#include <math.h>

// Problem constants
static constexpr int BN = 4;            // batch
static constexpr int NC = 21;           // classes
static constexpr int H  = 512;
static constexpr int W  = 512;
static constexpr int P  = 171;          // pooled H/W
static constexpr int NH = 169;          // cropped size P - (radius-1)
static constexpr int NPROB = BN * NC;   // 84
static constexpr int MM = NH * NH;      // 28561
static constexpr double D_ALPHA = 5e-4;
static constexpr float  CLIP_MIN = 1e-6f;
static constexpr int SPITCH = 172;      // smem pitch (mult of 4 for float4; 172/4=43 odd -> bank rotate)
static constexpr int SH = 16;           // strip height for k_cov
static constexpr int NSTRIP = (NH + SH - 1) / SH;  // 11

// Scratch (static device globals: no allocation allowed)
__device__ float  g_la[NPROB * P * P];      // pooled one-hot labels
__device__ float  g_pr[NPROB * P * P];      // pooled probs
__device__ double g_S[NPROB * 18 * 18];     // raw second-moment Gram (lower tri)
__device__ double g_sums[NPROB * 18];       // raw first moments (per shifted view)
__device__ double g_rmi[NPROB];
__device__ double g_bce;
__device__ double g_valid;

// lower-triangle 3x3-tile map of the 6x6 tile grid (21 tiles)
__constant__ int c_TI[21] = {0,1,1,2,2,2,3,3,3,3,4,4,4,4,4,5,5,5,5,5,5};
__constant__ int c_TJ[21] = {0,0,1,0,1,2,0,1,2,3,0,1,2,3,4,0,1,2,3,4,5};

// ---------------------------------------------------------------------------
__global__ void k_init() {
    int i = blockIdx.x * blockDim.x + threadIdx.x;
    if (i < NPROB * 18 * 18) g_S[i] = 0.0;
    if (i < NPROB * 18)      g_sums[i] = 0.0;
    if (i == 0) { g_bce = 0.0; g_valid = 0.0; }
}

// ---------------------------------------------------------------------------
// Fused: BCE partial sums + sigmoid + one-hot + 3x3/s3/p1 maxpool.
// Block = (py, n). Labels + per-class logit rows staged in smem (coalesced),
// compute reads smem -> 4 sectors per warp-load instead of ~13.
__global__ void __launch_bounds__(192) k_pool_bce(const float* __restrict__ logits,
                                                  const int*   __restrict__ labels) {
    int py = blockIdx.x;        // 0..170
    int n  = blockIdx.y;        // 0..3
    int tid = threadIdx.x;

    __shared__ __align__(16) float slog[3][520];   // data at idx 4..515 (xx+4)
    __shared__ float smk[3][520];
    __shared__ int   slab[3][520];
    __shared__ float warp_b[6], warp_v[6];

    int y0 = py * 3 - 1;
    const int* lb = labels + (long)n * H * W;

    // stage labels -> mask + label id (idx = xx + 4, pads are mask 0)
    for (int i = tid; i < 3 * 520; i += 192) {
        int r = i / 520, x = i - r * 520;
        int xx = x - 4;
        int y  = y0 + r;
        bool v = ((unsigned)y < (unsigned)H) && ((unsigned)xx < (unsigned)W);
        int  l = v ? lb[y * W + xx] : NC;
        slab[r][x] = l;
        smk[r][x]  = (l < NC) ? 1.f : 0.f;
    }
    // zero pad columns of slog once (never overwritten by staging)
    if (tid < 24) {
        int r = tid / 8, j = tid - r * 8;
        int x = (j < 4) ? j : 512 + j;
        slog[r][x] = 0.f;
    }
    __syncthreads();

    int  px  = tid;
    bool act = px < P;
    float mk[9]; int lab[9];
    float valid_part = 0.f, bce_part = 0.f;
    if (act) {
#pragma unroll
        for (int k = 0; k < 9; k++) {
            int r = k / 3, dx = k % 3;
            int idx = 3 * px + 3 + dx;
            mk[k]  = smk[r][idx];
            lab[k] = slab[r][idx];
            valid_part += mk[k];       // windows partition the input pixels
        }
    }
    bool rv[3];
#pragma unroll
    for (int r = 0; r < 3; r++) rv[r] = (unsigned)(y0 + r) < (unsigned)H;

    long ppp = (long)P * P;
    for (int c = 0; c < NC; c++) {
        __syncthreads();   // previous class compute finished before overwrite
        const float* lg = logits + (long)(n * NC + c) * H * W;
        for (int i = tid; i < 384; i += 192) {
            int r = i >> 7, j = i & 127;
            float4 v = make_float4(0.f, 0.f, 0.f, 0.f);
            if (rv[r]) v = ((const float4*)(lg + (long)(y0 + r) * W))[j];
            *(float4*)(&slog[r][4 + 4 * j]) = v;
        }
        __syncthreads();
        if (act) {
            float mla = 0.f, mpr = 0.f;
#pragma unroll
            for (int k = 0; k < 9; k++) {
                int r = k / 3, dx = k % 3;
                float xv = slog[r][3 * px + 3 + dx];
                float m  = mk[k];
                float t1 = (lab[k] == c) ? m : 0.f;
                float ax = fabsf(xv);
                float e  = __expf(-ax);
                bce_part += (fmaxf(xv, 0.f) - xv * t1 + __logf(1.f + e)) * m;
                float rc  = __fdividef(1.f, 1.f + e);
                float sig = (xv >= 0.f) ? rc : e * rc;
                float pb  = fmaf(sig, m, CLIP_MIN);
                mpr = fmaxf(mpr, pb);     // every window has >=4 valid pixels
                mla = fmaxf(mla, t1);
            }
            long o = (long)(n * NC + c) * ppp + (long)py * P + px;
            g_la[o] = mla;
            g_pr[o] = mpr;
        }
    }

    // block reduce bce / valid
#pragma unroll
    for (int off = 16; off > 0; off >>= 1) {
        bce_part   += __shfl_down_sync(0xffffffffu, bce_part,   off);
        valid_part += __shfl_down_sync(0xffffffffu, valid_part, off);
    }
    int wid = tid >> 5, lane = tid & 31;
    if (lane == 0) { warp_b[wid] = bce_part; warp_v[wid] = valid_part; }
    __syncthreads();
    if (tid == 0) {
        float b = 0.f, v = 0.f;
#pragma unroll
        for (int w = 0; w < 6; w++) { b += warp_b[w]; v += warp_v[w]; }
        atomicAdd(&g_bce,   (double)b);
        atomicAdd(&g_valid, (double)v);
    }
}

// ---------------------------------------------------------------------------
// First moments of the 9 shifted views (strip-parallel, warp-reduced).
__global__ void __launch_bounds__(256) k_sums() {
    int p = blockIdx.x;
    int s = blockIdx.y;
    int ylo = s * 22, yhi = min(P, ylo + 22);
    const float* la = g_la + p * P * P;
    const float* pr = g_pr + p * P * P;
    float sl[9], sp[9];
#pragma unroll
    for (int d = 0; d < 9; d++) { sl[d] = 0.f; sp[d] = 0.f; }
    for (int i = ylo * P + threadIdx.x; i < yhi * P; i += 256) {
        int y = i / P, x = i - y * P;
        float vl = la[i], vp = pr[i];
#pragma unroll
        for (int d = 0; d < 9; d++) {
            int dy = d / 3, dx = d % 3;
            if ((unsigned)(y - dy) < (unsigned)NH && (unsigned)(x - dx) < (unsigned)NH) {
                sl[d] += vl; sp[d] += vp;
            }
        }
    }
    __shared__ double sd[18];
    if (threadIdx.x < 18) sd[threadIdx.x] = 0.0;
#pragma unroll
    for (int d = 0; d < 9; d++) {
#pragma unroll
        for (int off = 16; off > 0; off >>= 1) {
            sl[d] += __shfl_down_sync(0xffffffffu, sl[d], off);
            sp[d] += __shfl_down_sync(0xffffffffu, sp[d], off);
        }
    }
    __syncthreads();
    if ((threadIdx.x & 31) == 0) {
#pragma unroll
        for (int d = 0; d < 9; d++) {
            atomicAdd(&sd[d],     (double)sl[d]);
            atomicAdd(&sd[9 + d], (double)sp[d]);
        }
    }
    __syncthreads();
    if (threadIdx.x < 18) atomicAdd(&g_sums[p * 18 + threadIdx.x], sd[threadIdx.x]);
}

// ---------------------------------------------------------------------------
// Gram matrix S = X X^T lower triangle, X = [18 x 28561].
// Sliding window over 6 row-streams; float4 loads: 2 LDS.128 per 4 steps.
__global__ void __launch_bounds__(192) k_cov() {
    int p     = blockIdx.x;
    int strip = blockIdx.y;
    int ys = strip * SH;
    int sh = min(SH, NH - ys);

    __shared__ __align__(16) float sla[(SH + 2) * SPITCH];
    __shared__ __align__(16) float spr[(SH + 2) * SPITCH];
    __shared__ double sacc[189];

    int tid = threadIdx.x;
    const float* la = g_la + p * P * P;
    const float* pr = g_pr + p * P * P;

    int nrows = sh + 2;
    for (int i = tid; i < nrows * P; i += 192) {
        int r = i / P, x = i - r * P;
        sla[r * SPITCH + x] = la[(ys + r) * P + x];
        spr[r * SPITCH + x] = pr[(ys + r) * P + x];
    }
    __syncthreads();

    bool active = tid < 189;
    float f[9];
#pragma unroll
    for (int q = 0; q < 9; q++) f[q] = 0.f;

    if (active) {
        int tile = tid / 9, mg = tid % 9;
        int ti = c_TI[tile], tj = c_TJ[tile];
        const float* baseA = ((ti < 3) ? sla : spr) + (ti % 3) * SPITCH;
        const float* baseB = ((tj < 3) ? sla : spr) + (tj % 3) * SPITCH;
        int xs = mg * 20;            // 4-aligned
        int xe = min(NH, xs + 20);   // 20 steps (mg<8) or 9 (mg=8)

#define CSTEP(a0,a1,a2,b0,b1,b2)                          \
        { f[0] += (a0)*(b0); f[1] += (a0)*(b1); f[2] += (a0)*(b2); \
          f[3] += (a1)*(b0); f[4] += (a1)*(b1); f[5] += (a1)*(b2); \
          f[6] += (a2)*(b0); f[7] += (a2)*(b1); f[8] += (a2)*(b2); }

        for (int y = 0; y < sh; y++) {
            const float* rA = baseA + y * SPITCH;
            const float* rB = baseB + y * SPITCH;
            float4 A = *(const float4*)(rA + xs);
            float4 B = *(const float4*)(rB + xs);
            int x = xs;
            for (; x + 4 <= xe; x += 4) {
                float4 An = *(const float4*)(rA + x + 4);
                float4 Bn = *(const float4*)(rB + x + 4);
                CSTEP(A.x, A.y, A.z,  B.x, B.y, B.z);
                CSTEP(A.y, A.z, A.w,  B.y, B.z, B.w);
                CSTEP(A.z, A.w, An.x, B.z, B.w, Bn.x);
                CSTEP(A.w, An.x, An.y, B.w, Bn.x, Bn.y);
                A = An; B = Bn;
            }
            for (; x < xe; x++) {        // <=3 scalar tail steps (mg==8 only)
                CSTEP(A.x, A.y, A.z, B.x, B.y, B.z);
                A.x = A.y; A.y = A.z; A.z = A.w;
                B.x = B.y; B.y = B.z; B.z = B.w;
            }
        }
#undef CSTEP
    }

    if (tid < 189) sacc[tid] = 0.0;
    __syncthreads();
    if (active) {
        int tile = tid / 9;
#pragma unroll
        for (int q = 0; q < 9; q++) atomicAdd(&sacc[tile * 9 + q], (double)f[q]);
    }
    __syncthreads();
    if (tid < 189) {
        int tl = tid / 9, q = tid - tl * 9;
        int i = c_TI[tl] * 3 + q / 3;
        int j = c_TJ[tl] * 3 + q % 3;
        atomicAdd(&g_S[p * 324 + i * 18 + j], sacc[tid]);
    }
}

// ---------------------------------------------------------------------------
// Warp-parallel 9x9 Cholesky (lower, in place, smem doubles)
__device__ __forceinline__ void chol9(double* A, int lane) {
    for (int k = 0; k < 9; k++) {
        if (lane == 0) A[k * 9 + k] = sqrt(A[k * 9 + k]);
        __syncwarp();
        double dk = A[k * 9 + k];
        if (lane > k && lane < 9) A[lane * 9 + k] /= dk;
        __syncwarp();
        for (int idx = lane; idx < 81; idx += 32) {
            int i = idx / 9, j = idx % 9;
            if (j > k && j <= i) A[i * 9 + j] -= A[i * 9 + k] * A[j * 9 + k];
        }
        __syncwarp();
    }
}

// One warp per (n,c): covariances from raw moments, Cholesky solve, logdet.
__global__ void __launch_bounds__(32) k_solve() {
    int p    = blockIdx.x;
    int lane = threadIdx.x;
    __shared__ double A[81], B[81], C2[81], V[81];
    const double* S  = g_S    + p * 324;
    const double* sm = g_sums + p * 18;
    const double invM = 1.0 / (double)MM;
    for (int idx = lane; idx < 81; idx += 32) {
        int i = idx / 9, j = idx % 9;
        int a = 9 + i, b = 9 + j;
        int hi = a > b ? a : b, lo = a > b ? b : a;
        A[idx] = S[hi * 18 + lo] - sm[a] * sm[b] * invM + (i == j ? D_ALPHA : 0.0); // pr_cov+aI
        B[idx] = S[(9 + j) * 18 + i] - sm[i] * sm[9 + j] * invM;                    // cross[d][e]
        hi = i > j ? i : j; lo = i > j ? j : i;
        C2[idx] = S[hi * 18 + lo] - sm[i] * sm[j] * invM;                           // la_cov
    }
    __syncwarp();
    chol9(A, lane);
    // forward solve L V = cross^T   (column d per lane)
    if (lane < 9) {
        int d = lane;
        for (int e = 0; e < 9; e++) {
            double t = B[d * 9 + e];
            for (int j = 0; j < e; j++) t -= A[e * 9 + j] * V[j * 9 + d];
            V[e * 9 + d] = t / A[e * 9 + e];
        }
    }
    __syncwarp();
    // appro_var = la_cov - V^T V + aI   (reuse B)
    for (int idx = lane; idx < 81; idx += 32) {
        int i = idx / 9, j = idx % 9;
        double t = C2[idx];
#pragma unroll
        for (int k = 0; k < 9; k++) t -= V[k * 9 + i] * V[k * 9 + j];
        if (i == j) t += D_ALPHA;
        B[idx] = t;
    }
    __syncwarp();
    chol9(B, lane);
    double lsum = (lane < 9) ? log(B[lane * 9 + lane]) : 0.0;  // 0.5*logdet
    for (int off = 16; off > 0; off >>= 1)
        lsum += __shfl_down_sync(0xffffffffu, lsum, off);
    if (lane == 0) g_rmi[p] = lsum;
}

// ---------------------------------------------------------------------------
__global__ void k_final(float* out) {
    __shared__ double sm[128];
    int t = threadIdx.x;
    sm[t] = (t < NPROB) ? g_rmi[t] : 0.0;
    __syncthreads();
    for (int s = 64; s > 0; s >>= 1) {
        if (t < s) sm[t] += sm[t + s];
        __syncthreads();
    }
    if (t == 0) {
        double rmi = sm[0] / 36.0;                  // mean over batch(4)/half_d(9)
        double bce = g_bce / (g_valid + 1.0);
        out[0] = (float)(0.5 * bce + 0.5 * rmi);
    }
}

// ---------------------------------------------------------------------------
extern "C" void kernel_launch(void* const* d_in, const int* in_sizes, int n_in,
                              void* d_out, int out_size) {
    const float* logits = (const float*)d_in[0];
    const int*   labels = (const int*)d_in[1];
    float* out = (float*)d_out;

    k_init<<<(NPROB * 324 + 255) / 256, 256>>>();
    k_pool_bce<<<dim3(P, BN), 192>>>(logits, labels);
    k_sums<<<dim3(NPROB, 8), 256>>>();
    k_cov<<<dim3(NPROB, NSTRIP), 192>>>();
    k_solve<<<NPROB, 32>>>();
    k_final<<<1, 128>>>(out);
}

// round 4
// speedup vs baseline: 4.5132x; 1.6664x over previous
#include <cuda_runtime.h>
#include <math.h>

typedef unsigned long long ull;

// Problem constants
static constexpr int BN = 4;            // batch
static constexpr int NC = 21;           // classes
static constexpr int H  = 512;
static constexpr int W  = 512;
static constexpr int P  = 171;          // pooled H/W
static constexpr int NH = 169;          // cropped size P - (radius-1)
static constexpr int NPROB = BN * NC;   // 84
static constexpr int MM = NH * NH;      // 28561
static constexpr double D_ALPHA = 5e-4;
static constexpr float  CLIP_MIN = 1e-6f;
static constexpr int SPITCH = 172;      // smem pitch (floats, mult of 4 -> aligned float4)
static constexpr int SH = 16;           // strip height for k_cov
static constexpr int NSTRIP = (NH + SH - 1) / SH;  // 11

// Scratch (static device globals: no allocation allowed)
__device__ float  g_la[NPROB * P * P];      // pooled one-hot labels
__device__ float  g_pr[NPROB * P * P];      // pooled probs
__device__ double g_S[NPROB * 18 * 18];     // raw second-moment Gram
__device__ double g_sums[NPROB * 18];       // raw first moments (per shifted view)
__device__ double g_rmi[NPROB];
__device__ double g_bce;
__device__ double g_valid;

// stream-pair-block map: 6 lower-tri pairs of the 3 stream-groups
__constant__ int c_PBI[6] = {0, 1, 1, 2, 2, 2};
__constant__ int c_PBJ[6] = {0, 0, 1, 0, 1, 2};

// ---------------------------------------------------------------------------
__global__ void k_init() {
    int i = blockIdx.x * blockDim.x + threadIdx.x;
    if (i < NPROB * 18 * 18) g_S[i] = 0.0;
    if (i < NPROB * 18)      g_sums[i] = 0.0;
    if (i == 0) { g_bce = 0.0; g_valid = 0.0; }
}

// ---------------------------------------------------------------------------
// Fused: BCE partial sums + sigmoid + one-hot + 3x3/s3/p1 maxpool.
// Sigmoid is monotone -> pooled prob max = sigmoid(max valid logit) + 1e-6:
// only 1 rcp per WINDOW instead of 9.
__global__ void __launch_bounds__(192) k_pool_bce(const float* __restrict__ logits,
                                                  const int*   __restrict__ labels) {
    int py = blockIdx.x;        // 0..170
    int n  = blockIdx.y;        // 0..3
    int tid = threadIdx.x;

    __shared__ __align__(16) float slog[3][520];   // data at idx 4..515
    __shared__ float smk[3][520];
    __shared__ int   slab[3][520];
    __shared__ float warp_b[6], warp_v[6];

    int y0 = py * 3 - 1;
    const int* lb = labels + (long)n * H * W;

    for (int i = tid; i < 3 * 520; i += 192) {
        int r = i / 520, x = i - r * 520;
        int xx = x - 4;
        int y  = y0 + r;
        bool v = ((unsigned)y < (unsigned)H) && ((unsigned)xx < (unsigned)W);
        int  l = v ? lb[y * W + xx] : NC;
        slab[r][x] = l;
        smk[r][x]  = (l < NC) ? 1.f : 0.f;
    }
    if (tid < 24) {
        int r = tid / 8, j = tid - r * 8;
        int x = (j < 4) ? j : 512 + j;
        slog[r][x] = 0.f;
    }
    __syncthreads();

    int  px  = tid;
    bool act = px < P;
    float mk[9]; int lab[9];
    float valid_part = 0.f, bce_part = 0.f;
    if (act) {
#pragma unroll
        for (int k = 0; k < 9; k++) {
            int r = k / 3, dx = k % 3;
            int idx = 3 * px + 3 + dx;
            mk[k]  = smk[r][idx];
            lab[k] = slab[r][idx];
            valid_part += mk[k];
        }
    }
    bool rv[3];
#pragma unroll
    for (int r = 0; r < 3; r++) rv[r] = (unsigned)(y0 + r) < (unsigned)H;

    long ppp = (long)P * P;
    for (int c = 0; c < NC; c++) {
        __syncthreads();
        const float* lg = logits + (long)(n * NC + c) * H * W;
        for (int i = tid; i < 384; i += 192) {
            int r = i >> 7, j = i & 127;
            float4 v = make_float4(0.f, 0.f, 0.f, 0.f);
            if (rv[r]) v = ((const float4*)(lg + (long)(y0 + r) * W))[j];
            *(float4*)(&slog[r][4 + 4 * j]) = v;
        }
        __syncthreads();
        if (act) {
            float mla = 0.f, mv = -1e30f;
#pragma unroll
            for (int k = 0; k < 9; k++) {
                int r = k / 3, dx = k % 3;
                float xv = slog[r][3 * px + 3 + dx];
                float m  = mk[k];
                float t1 = (lab[k] == c) ? m : 0.f;
                float ax = fabsf(xv);
                float e  = __expf(-ax);
                bce_part += (fmaxf(xv, 0.f) - xv * t1 + __logf(1.f + e)) * m;
                mla = fmaxf(mla, t1);
                mv  = fmaxf(mv, (m > 0.f) ? xv : -1e30f);
            }
            // single sigmoid on the window max of valid logits
            float em  = __expf(-fabsf(mv));
            float rc  = __fdividef(1.f, 1.f + em);
            float sig = (mv >= 0.f) ? rc : em * rc;   // mv=-1e30 -> 0
            long o = (long)(n * NC + c) * ppp + (long)py * P + px;
            g_la[o] = mla;
            g_pr[o] = sig + CLIP_MIN;
        }
    }

#pragma unroll
    for (int off = 16; off > 0; off >>= 1) {
        bce_part   += __shfl_down_sync(0xffffffffu, bce_part,   off);
        valid_part += __shfl_down_sync(0xffffffffu, valid_part, off);
    }
    int wid = tid >> 5, lane = tid & 31;
    if (lane == 0) { warp_b[wid] = bce_part; warp_v[wid] = valid_part; }
    __syncthreads();
    if (tid == 0) {
        float b = 0.f, v = 0.f;
#pragma unroll
        for (int w = 0; w < 6; w++) { b += warp_b[w]; v += warp_v[w]; }
        atomicAdd(&g_bce,   (double)b);
        atomicAdd(&g_valid, (double)v);
    }
}

// ---------------------------------------------------------------------------
// f32x2 helpers
__device__ __forceinline__ ull pk2(float lo, float hi) {
    ull r; asm("mov.b64 %0, {%1, %2};" : "=l"(r) : "f"(lo), "f"(hi)); return r;
}
#define FMA2(d, a, b) asm("fma.rn.f32x2 %0, %1, %2, %0;" : "+l"(d) : "l"(a), "l"(b))

// One step: acc[j*9+l*3+m] += PA[l-pos] * dup(Bj[m-pos]); PA packed over the
// two A-streams, so each FMA2 covers 2 Gram entries.
#define DOSTEP(PL0, PL1, PL2, B00, B01, B02, B10, B11, B12) do {              \
    ull d00 = pk2((B00),(B00)), d01 = pk2((B01),(B01)), d02 = pk2((B02),(B02)); \
    ull d10 = pk2((B10),(B10)), d11 = pk2((B11),(B11)), d12 = pk2((B12),(B12)); \
    FMA2(acc[0],  PL0, d00); FMA2(acc[1],  PL0, d01); FMA2(acc[2],  PL0, d02); \
    FMA2(acc[3],  PL1, d00); FMA2(acc[4],  PL1, d01); FMA2(acc[5],  PL1, d02); \
    FMA2(acc[6],  PL2, d00); FMA2(acc[7],  PL2, d01); FMA2(acc[8],  PL2, d02); \
    FMA2(acc[9],  PL0, d10); FMA2(acc[10], PL0, d11); FMA2(acc[11], PL0, d12); \
    FMA2(acc[12], PL1, d10); FMA2(acc[13], PL1, d11); FMA2(acc[14], PL1, d12); \
    FMA2(acc[15], PL2, d10); FMA2(acc[16], PL2, d11); FMA2(acc[17], PL2, d12); \
} while (0)

#define PAW(t) ((t) < 4 ? PA[(t)]  : PAn[(t) - 4])
#define B0W(t) ((t) < 4 ? b0c[(t)] : b0n[(t) - 4])
#define B1W(t) ((t) < 4 ? b1c[(t)] : b1n[(t) - 4])

// Gram matrix of the 18 shifted views via 6 stream-pair-blocks; also folds in
// the per-view first-moment sums (row-total minus edges trick).
__global__ void __launch_bounds__(96, 6) k_cov() {
    int p     = blockIdx.x;
    int strip = blockIdx.y;
    int ys = strip * SH;
    int sh = min(SH, NH - ys);

    __shared__ __align__(16) float sbuf[2 * 18 * SPITCH];  // la rows | pr rows
    __shared__ float srs[36];
    float* sla = sbuf;
    float* spr = sbuf + 18 * SPITCH;

    int tid = threadIdx.x;
    int row = tid & 15;
    int pb  = tid >> 4;
    const float* la = g_la + p * P * P;
    const float* pr = g_pr + p * P * P;

    // stage sh+2 rows of both maps
    int nrows = sh + 2;
    for (int i = tid; i < nrows * P; i += 96) {
        int r = i / P, x = i - r * P;
        sla[r * SPITCH + x] = la[(ys + r) * P + x];
        spr[r * SPITCH + x] = pr[(ys + r) * P + x];
    }
    __syncthreads();

    ull acc[18];
#pragma unroll
    for (int k = 0; k < 18; k++) acc[k] = 0ULL;

    if (row < sh) {
        int gi = c_PBI[pb], gj = c_PBJ[pb];
        int sA0 = 2 * gi, sA1 = 2 * gi + 1, sB0 = 2 * gj, sB1 = 2 * gj + 1;
        const float* pA0 = ((sA0 < 3) ? sla : spr) + ((sA0 < 3 ? sA0 : sA0 - 3) + row) * SPITCH;
        const float* pA1 = ((sA1 < 3) ? sla : spr) + ((sA1 < 3 ? sA1 : sA1 - 3) + row) * SPITCH;
        const float* pB0 = ((sB0 < 3) ? sla : spr) + ((sB0 < 3 ? sB0 : sB0 - 3) + row) * SPITCH;
        const float* pB1 = ((sB1 < 3) ? sla : spr) + ((sB1 < 3 ? sB1 : sB1 - 3) + row) * SPITCH;

        float4 va = *(const float4*)(pA0);
        float4 vb = *(const float4*)(pA1);
        ull PA[4] = { pk2(va.x, vb.x), pk2(va.y, vb.y), pk2(va.z, vb.z), pk2(va.w, vb.w) };
        float4 v0 = *(const float4*)(pB0);
        float4 v1 = *(const float4*)(pB1);
        float b0c[4] = { v0.x, v0.y, v0.z, v0.w };
        float b1c[4] = { v1.x, v1.y, v1.z, v1.w };

        for (int x = 0; x + 4 <= NH - 1; x += 4) {   // x = 0..164, steps 0..167
            va = *(const float4*)(pA0 + x + 4);
            vb = *(const float4*)(pA1 + x + 4);
            ull PAn[4] = { pk2(va.x, vb.x), pk2(va.y, vb.y), pk2(va.z, vb.z), pk2(va.w, vb.w) };
            v0 = *(const float4*)(pB0 + x + 4);
            v1 = *(const float4*)(pB1 + x + 4);
            float b0n[4] = { v0.x, v0.y, v0.z, v0.w };
            float b1n[4] = { v1.x, v1.y, v1.z, v1.w };
#pragma unroll
            for (int s = 0; s < 4; s++)
                DOSTEP(PAW(s), PAW(s + 1), PAW(s + 2),
                       B0W(s), B0W(s + 1), B0W(s + 2),
                       B1W(s), B1W(s + 1), B1W(s + 2));
#pragma unroll
            for (int t = 0; t < 4; t++) { PA[t] = PAn[t]; b0c[t] = b0n[t]; b1c[t] = b1n[t]; }
        }
        // tail step x = 168 (operands are positions 168..170)
        DOSTEP(PA[0], PA[1], PA[2], b0c[0], b0c[1], b0c[2], b1c[0], b1c[1], b1c[2]);
    }

    // ---- folded first-moment sums (row totals minus edge elements) ----
    if (tid < 36) {
        int mp = tid / 18, r = tid % 18;
        float T = 0.f;
        if (r < sh + 2) {
            const float* rowp = (mp ? spr : sla) + r * SPITCH;
            for (int x = 0; x < P; x++) T += rowp[x];
        }
        srs[tid] = T;
    }
    __syncthreads();
    if (tid < 18) {
        int mp = tid / 9, dd = tid % 9, dy = dd / 3, dx = dd % 3;
        const float* base = mp ? spr : sla;
        float part = 0.f;
        for (int yl = 0; yl < sh; yl++) {
            int r = yl + dy;
            const float* rowp = base + r * SPITCH;
            float T = srs[mp * 18 + r];
            float rs = (dx == 0) ? T - rowp[169] - rowp[170]
                     : (dx == 1) ? T - rowp[0]   - rowp[170]
                     :             T - rowp[0]   - rowp[1];
            part += rs;
        }
        atomicAdd(&g_sums[p * 18 + tid], (double)part);
    }
    __syncthreads();

    // ---- reduce 96x36 partials over the 16 rows, flush to g_S ----
    float* red = sbuf;             // overlay (96*36 = 3456 floats)
#pragma unroll
    for (int k = 0; k < 18; k++) {
        float lo, hi;
        asm("mov.b64 {%0, %1}, %2;" : "=f"(lo), "=f"(hi) : "l"(acc[k]));
        red[tid * 36 + k]      = lo;   // i = 0 (stream 2gi)
        red[tid * 36 + 18 + k] = hi;   // i = 1 (stream 2gi+1)
    }
    __syncthreads();
    for (int o = tid; o < 216; o += 96) {
        int pb2 = o / 36, q = o % 36;
        float ssum = 0.f;
#pragma unroll
        for (int r2 = 0; r2 < 16; r2++) ssum += red[(pb2 * 16 + r2) * 36 + q];
        int i = q / 18, k = q % 18;
        int j = k / 9, l = (k % 9) / 3, m = k % 3;
        int a = (2 * c_PBI[pb2] + i) * 3 + l;
        int b = (2 * c_PBJ[pb2] + j) * 3 + m;
        atomicAdd(&g_S[p * 324 + a * 18 + b], (double)ssum);
    }
}

// ---------------------------------------------------------------------------
// Warp-parallel 9x9 Cholesky (fp32; matrices are well-conditioned)
__device__ __forceinline__ void chol9f(float* A, int lane) {
    for (int k = 0; k < 9; k++) {
        if (lane == 0) A[k * 9 + k] = sqrtf(A[k * 9 + k]);
        __syncwarp();
        float rd = __fdividef(1.f, A[k * 9 + k]);
        if (lane > k && lane < 9) A[lane * 9 + k] *= rd;
        __syncwarp();
        for (int idx = lane; idx < 81; idx += 32) {
            int i = idx / 9, j = idx % 9;
            if (j > k && j <= i) A[i * 9 + j] -= A[i * 9 + k] * A[j * 9 + k];
        }
        __syncwarp();
    }
}

// One warp per (n,c): assemble covariances in double, solve in float.
__global__ void __launch_bounds__(32) k_solve() {
    int p    = blockIdx.x;
    int lane = threadIdx.x;
    __shared__ float A[81], B[81], C2[81], V[81];
    const double* S  = g_S    + p * 324;
    const double* sm = g_sums + p * 18;
    const double invM = 1.0 / (double)MM;
    for (int idx = lane; idx < 81; idx += 32) {
        int i = idx / 9, j = idx % 9;
        int a = 9 + i, b = 9 + j;
        int hi = a > b ? a : b, lo = a > b ? b : a;
        A[idx] = (float)(S[hi * 18 + lo] - sm[a] * sm[b] * invM + (i == j ? D_ALPHA : 0.0));
        B[idx] = (float)(S[(9 + j) * 18 + i] - sm[i] * sm[9 + j] * invM);   // cross[d][e]
        hi = i > j ? i : j; lo = i > j ? j : i;
        C2[idx] = (float)(S[hi * 18 + lo] - sm[i] * sm[j] * invM);          // la_cov
    }
    __syncwarp();
    chol9f(A, lane);
    if (lane < 9) {   // forward solve L V = cross^T (column d per lane)
        int d = lane;
        for (int e = 0; e < 9; e++) {
            float t = B[d * 9 + e];
            for (int j = 0; j < e; j++) t -= A[e * 9 + j] * V[j * 9 + d];
            V[e * 9 + d] = t * __fdividef(1.f, A[e * 9 + e]);
        }
    }
    __syncwarp();
    for (int idx = lane; idx < 81; idx += 32) {   // appro_var = la_cov - V^T V + aI
        int i = idx / 9, j = idx % 9;
        float t = C2[idx];
#pragma unroll
        for (int k = 0; k < 9; k++) t -= V[k * 9 + i] * V[k * 9 + j];
        if (i == j) t += (float)D_ALPHA;
        B[idx] = t;
    }
    __syncwarp();
    chol9f(B, lane);
    float lsum = (lane < 9) ? logf(B[lane * 9 + lane]) : 0.f;   // 0.5*logdet
    for (int off = 16; off > 0; off >>= 1)
        lsum += __shfl_down_sync(0xffffffffu, lsum, off);
    if (lane == 0) g_rmi[p] = (double)lsum;
}

// ---------------------------------------------------------------------------
__global__ void k_final(float* out) {
    __shared__ double sm[128];
    int t = threadIdx.x;
    sm[t] = (t < NPROB) ? g_rmi[t] : 0.0;
    __syncthreads();
    for (int s = 64; s > 0; s >>= 1) {
        if (t < s) sm[t] += sm[t + s];
        __syncthreads();
    }
    if (t == 0) {
        double rmi = sm[0] / 36.0;                  // mean over batch(4)/half_d(9)
        double bce = g_bce / (g_valid + 1.0);
        out[0] = (float)(0.5 * bce + 0.5 * rmi);
    }
}

// ---------------------------------------------------------------------------
extern "C" void kernel_launch(void* const* d_in, const int* in_sizes, int n_in,
                              void* d_out, int out_size) {
    const float* logits = (const float*)d_in[0];
    const int*   labels = (const int*)d_in[1];
    float* out = (float*)d_out;

    k_init<<<(NPROB * 324 + 255) / 256, 256>>>();
    k_pool_bce<<<dim3(P, BN), 192>>>(logits, labels);
    k_cov<<<dim3(NPROB, NSTRIP), 96>>>();
    k_solve<<<NPROB, 32>>>();
    k_final<<<1, 128>>>(out);
}